// round 15
// baseline (speedup 1.0000x reference)
#include <cuda_runtime.h>
#include <cstdint>

// GCNConv: N=10000 nodes, E=160000 edges, D_in=D_out=512
#define MAX_N 10000
#define MAX_E 160000
#define D     512
#define D4    128

// ---------------- device scratch ----------------
__device__ float g_h [(size_t)MAX_N * D];   // h = x @ W (20 MB)
__device__ float g_wb[(size_t)D * D];       // W pre-converted to tf32 bits (1 MB)
__device__ float g_deg[MAX_N];
__device__ float g_dinv[MAX_N];
// CSR by target node
__device__ int   g_cnt[MAX_N];
__device__ int   g_rowptr[MAX_N + 1];
__device__ int   g_cursor[MAX_N];
__device__ int   g_src[MAX_E];
__device__ float g_wn[MAX_E];

// ---------------- fused init: deg/cnt init + W tf32 conversion ----------------
__device__ __forceinline__ float f2tf32f(float f) {
    uint32_t r;
    asm("cvt.rna.tf32.f32 %0, %1;" : "=r"(r) : "f"(f));
    return __uint_as_float(r);
}
__global__ void k_init(const float* __restrict__ W, float* __restrict__ wb,
                       int n, int w4) {
    int i = blockIdx.x * blockDim.x + threadIdx.x;
    if (i < n) { g_deg[i] = 1.0f; g_cnt[i] = 0; }
    if (i < w4) {
        float4 v = ((const float4*)W)[i];
        v.x = f2tf32f(v.x); v.y = f2tf32f(v.y);
        v.z = f2tf32f(v.z); v.w = f2tf32f(v.w);
        ((float4*)wb)[i] = v;
    }
}

__global__ void k_deg_acc(const int* __restrict__ ei,
                          const float* __restrict__ ew, int E) {
    int e = blockIdx.x * blockDim.x + threadIdx.x;
    if (e < E) {
        int c = ei[E + e];
        atomicAdd(&g_deg[c], ew[e]);
        atomicAdd(&g_cnt[c], 1);
    }
}

// ---------------- scan (rowptr + cursor) fused with dinv ----------------
__global__ void k_scan(int n, int E) {
    __shared__ int s[1024];
    int t = threadIdx.x;
    int per = (n + 1023) >> 10;
    int beg = t * per;
    int end = min(beg + per, n);
    int lsum = 0;
    for (int i = beg; i < end; i++) {
        lsum += g_cnt[i];
        float d = g_deg[i];
        g_dinv[i] = (d > 0.0f) ? rsqrtf(d) : 0.0f;
    }
    s[t] = lsum;
    __syncthreads();
    #pragma unroll
    for (int off = 1; off < 1024; off <<= 1) {
        int v = (t >= off) ? s[t - off] : 0;
        __syncthreads();
        s[t] += v;
        __syncthreads();
    }
    int pre = (t == 0) ? 0 : s[t - 1];
    for (int i = beg; i < end; i++) {
        g_rowptr[i] = pre;
        g_cursor[i] = pre;
        pre += g_cnt[i];
    }
    if (t == 1023) g_rowptr[n] = E;
}

// ---------------- CSR fill (stores precomputed norm) ----------------
__global__ void k_fill(const int* __restrict__ ei, const float* __restrict__ ew,
                       int E) {
    int e = blockIdx.x * blockDim.x + threadIdx.x;
    if (e >= E) return;
    int r = ei[e];
    int c = ei[E + e];
    int pos = atomicAdd(&g_cursor[c], 1);
    g_src[pos] = r;
    g_wn[pos]  = g_dinv[r] * ew[e] * g_dinv[c];
}

// ---------------- tf32 tensor-core GEMM, 64x64 warp tiles, 3-stage ----------------
// A = raw fp32 x (HW truncates to tf32); B = rna-converted W.
#define BM 128
#define BN 128
#define BK 16
#define KT (D / BK)
#define AS 20
#define BS 136
#define NSTAGE 3
#define A_STAGE (BM * AS)            // floats per A stage
#define B_STAGE (BK * BS)            // floats per B stage
#define SMEM_FLOATS (NSTAGE * (A_STAGE + B_STAGE))

__device__ __forceinline__ void mma_tf32(float c[4], const uint32_t a[4],
                                         uint32_t b0, uint32_t b1) {
    asm volatile(
        "mma.sync.aligned.m16n8k8.row.col.f32.tf32.tf32.f32 "
        "{%0,%1,%2,%3}, {%4,%5,%6,%7}, {%8,%9}, {%0,%1,%2,%3};"
        : "+f"(c[0]), "+f"(c[1]), "+f"(c[2]), "+f"(c[3])
        : "r"(a[0]), "r"(a[1]), "r"(a[2]), "r"(a[3]), "r"(b0), "r"(b1));
}
__device__ __forceinline__ void cp16(uint32_t dst, const float* src, int bytes) {
    asm volatile("cp.async.cg.shared.global [%0], [%1], 16, %2;"
                 :: "r"(dst), "l"(src), "r"(bytes));
}

__global__ __launch_bounds__(128, 2)
void k_gemm_tc(const float* __restrict__ A, const float* __restrict__ B,
               float* __restrict__ H, int M) {
    extern __shared__ float smem[];
    float* AsBase = smem;                       // [NSTAGE][BM][AS]
    float* BsBase = smem + NSTAGE * A_STAGE;    // [NSTAGE][BK][BS]

    const int tid  = threadIdx.x;
    const int warp = tid >> 5, lane = tid & 31;
    const int g = lane >> 2, t = lane & 3;
    const int wy = warp >> 1;              // 0..1 (M dir)
    const int wx = warp & 1;               // 0..1 (N dir)
    const int m_warp = wy * 64;
    const int n_warp = wx * 64;
    const int m0 = blockIdx.y * BM;
    const int n0 = blockIdx.x * BN;

    uint32_t sA = (uint32_t)__cvta_generic_to_shared(AsBase);
    uint32_t sB = (uint32_t)__cvta_generic_to_shared(BsBase);

    float acc[4][8][4];
    #pragma unroll
    for (int mf = 0; mf < 4; mf++)
        #pragma unroll
        for (int nf = 0; nf < 8; nf++)
            #pragma unroll
            for (int i = 0; i < 4; i++) acc[mf][nf][i] = 0.0f;

    // 128 threads: 4 x 16B chunks each for A (8KB) and B (8KB)
    auto load_tiles = [&](int k0, int buf) {
        #pragma unroll
        for (int i = 0; i < 4; i++) {
            int c   = tid + i * 128;        // 0..511
            int row = c >> 2;               // 0..127
            int kq  = (c & 3) * 4;          // 0,4,8,12
            int gr  = m0 + row;
            const float* src = A + (size_t)gr * D + k0 + kq;
            uint32_t dst = sA + (uint32_t)((buf * A_STAGE + row * AS + kq) * 4);
            cp16(dst, src, (gr < M) ? 16 : 0);
        }
        #pragma unroll
        for (int i = 0; i < 4; i++) {
            int c   = tid + i * 128;        // 0..511
            int row = c >> 5;               // 0..15
            int nq  = (c & 31) * 4;         // 0..124
            const float* src = B + (size_t)(k0 + row) * D + n0 + nq;
            uint32_t dst = sB + (uint32_t)((buf * B_STAGE + row * BS + nq) * 4);
            cp16(dst, src, 16);
        }
    };

    // prologue: stages 0,1 in flight
    load_tiles(0, 0);
    asm volatile("cp.async.commit_group;");
    load_tiles(BK, 1);
    asm volatile("cp.async.commit_group;");

    for (int kt = 0; kt < KT; kt++) {
        asm volatile("cp.async.wait_group 1;");
        __syncthreads();

        int buf = kt % NSTAGE;
        const float* Asb = AsBase + buf * A_STAGE;
        const float* Bsb = BsBase + buf * B_STAGE;

        #pragma unroll
        for (int ks = 0; ks < 2; ks++) {
            const int kk = ks * 8;
            uint32_t a[4][4];
            #pragma unroll
            for (int mf = 0; mf < 4; mf++) {
                int r = m_warp + mf * 16 + g;
                a[mf][0] = __float_as_uint(Asb[r * AS + kk + t]);
                a[mf][1] = __float_as_uint(Asb[(r + 8) * AS + kk + t]);
                a[mf][2] = __float_as_uint(Asb[r * AS + kk + t + 4]);
                a[mf][3] = __float_as_uint(Asb[(r + 8) * AS + kk + t + 4]);
            }
            #pragma unroll
            for (int nf = 0; nf < 8; nf++) {
                int ncol = n_warp + nf * 8 + g;
                uint32_t b0 = __float_as_uint(Bsb[(kk + t) * BS + ncol]);
                uint32_t b1 = __float_as_uint(Bsb[(kk + t + 4) * BS + ncol]);
                #pragma unroll
                for (int mf = 0; mf < 4; mf++)
                    mma_tf32(acc[mf][nf], a[mf], b0, b1);
            }
        }

        // issue next load into stage (kt+2)%3 == (kt-1)%3 (safe: sync above
        // guarantees all threads finished computing that stage last iter)
        if (kt + 2 < KT) load_tiles((kt + 2) * BK, (kt + 2) % NSTAGE);
        asm volatile("cp.async.commit_group;");   // empty group ok at tail
    }

    #pragma unroll
    for (int mf = 0; mf < 4; mf++) {
        #pragma unroll
        for (int half = 0; half < 2; half++) {
            int r = m0 + m_warp + mf * 16 + g + half * 8;
            if (r >= M) continue;
            #pragma unroll
            for (int nf = 0; nf < 8; nf++) {
                int col = n0 + n_warp + nf * 8 + t * 2;
                *(float2*)(H + (size_t)r * D + col) =
                    make_float2(acc[mf][nf][half * 2 + 0],
                                acc[mf][nf][half * 2 + 1]);
            }
        }
    }
}

// ---------------- gather: one warp per target node ----------------
__global__ __launch_bounds__(256)
void k_gather(const float* __restrict__ bias, float* __restrict__ out, int n) {
    int w = (int)((blockIdx.x * blockDim.x + threadIdx.x) >> 5);
    int lane = threadIdx.x & 31;
    if (w >= n) return;

    int rs = g_rowptr[w];
    int re = g_rowptr[w + 1];
    float s = g_dinv[w];
    s = s * s;

    const float4* hp = (const float4*)g_h;
    const float4* bp = (const float4*)bias;

    float4 acc[4];
    #pragma unroll
    for (int i = 0; i < 4; i++) {
        int idx = lane + i * 32;
        float4 bv = bp[idx];
        float4 hv = hp[(size_t)w * D4 + idx];
        acc[i].x = bv.x + hv.x * s;
        acc[i].y = bv.y + hv.y * s;
        acc[i].z = bv.z + hv.z * s;
        acc[i].w = bv.w + hv.w * s;
    }

    for (int e = rs; e < re; e++) {
        int r = g_src[e];
        float nrm = g_wn[e];
        const float4* rp = hp + (size_t)r * D4;
        #pragma unroll
        for (int i = 0; i < 4; i++) {
            float4 v = rp[lane + i * 32];
            acc[i].x = fmaf(v.x, nrm, acc[i].x);
            acc[i].y = fmaf(v.y, nrm, acc[i].y);
            acc[i].z = fmaf(v.z, nrm, acc[i].z);
            acc[i].w = fmaf(v.w, nrm, acc[i].w);
        }
    }

    float4* op = (float4*)out + (size_t)w * D4;
    #pragma unroll
    for (int i = 0; i < 4; i++) op[lane + i * 32] = acc[i];
}

// ---------------- launch ----------------
extern "C" void kernel_launch(void* const* d_in, const int* in_sizes, int n_in,
                              void* d_out, int out_size) {
    const float* x  = (const float*)d_in[0];       // [N, 512]
    const int*   ei = (const int*)d_in[1];         // [2, E] int32
    const float* ew = (const float*)d_in[2];       // [E]
    const float* W  = (const float*)d_in[3];       // [512, 512]
    const float* b  = (const float*)d_in[4];       // [512]
    float* out = (float*)d_out;

    const int N = in_sizes[0] / D;   // 10000
    const int E = in_sizes[2];       // 160000

    float *h, *wb;
    cudaGetSymbolAddress((void**)&h,  g_h);
    cudaGetSymbolAddress((void**)&wb, g_wb);

    const int smem_bytes = SMEM_FLOATS * (int)sizeof(float);   // 56832
    cudaFuncSetAttribute(k_gemm_tc,
                         cudaFuncAttributeMaxDynamicSharedMemorySize, smem_bytes);

    // 1) fused: deg/cnt init + W tf32 conversion
    int w4 = D * D / 4;                         // 65536
    int init_n = (w4 > N) ? w4 : N;
    k_init<<<(init_n + 255) / 256, 256>>>(W, wb, N, w4);

    // 2) degree + histogram
    k_deg_acc<<<(E + 255) / 256, 256>>>(ei, ew, E);

    // 3) scan (rowptr/cursor) + dinv
    k_scan<<<1, 1024>>>(N, E);

    // 4) CSR fill with precomputed norms
    k_fill<<<(E + 255) / 256, 256>>>(ei, ew, E);

    // 5) h = x @ W (tensor cores, 3-stage pipeline)
    dim3 grid(D / BN, (N + BM - 1) / BM);       // (4, 79)
    k_gemm_tc<<<grid, 128, smem_bytes>>>(x, wb, h, N);

    // 6) gather: out = b + h[c]*dinv^2 + sum_e norm * h[src]
    int blocks = (N * 32 + 255) / 256;
    k_gather<<<blocks, 256>>>(b, out, N);
}

// round 16
// speedup vs baseline: 1.0042x; 1.0042x over previous
#include <cuda_runtime.h>
#include <cstdint>

// GCNConv: N=10000 nodes, E=160000 edges, D_in=D_out=512
#define MAX_N 10000
#define MAX_E 160000
#define D     512
#define D4    128

// ---------------- device scratch ----------------
__device__ float g_h [(size_t)MAX_N * D];   // h = x @ W (20 MB)
__device__ float g_wb[(size_t)D * D];       // W pre-converted to tf32 bits (1 MB)
__device__ float g_deg[MAX_N];
__device__ float g_dinv[MAX_N];
// CSR by target node
__device__ int   g_cnt[MAX_N];
__device__ int   g_rowptr[MAX_N + 1];
__device__ int   g_cursor[MAX_N];
__device__ int   g_src[MAX_E];
__device__ float g_wn[MAX_E];

// ---------------- fused init: deg/cnt init + W tf32 conversion ----------------
__device__ __forceinline__ float f2tf32f(float f) {
    uint32_t r;
    asm("cvt.rna.tf32.f32 %0, %1;" : "=r"(r) : "f"(f));
    return __uint_as_float(r);
}
__global__ void k_init(const float* __restrict__ W, float* __restrict__ wb,
                       int n, int w4) {
    int i = blockIdx.x * blockDim.x + threadIdx.x;
    if (i < n) { g_deg[i] = 1.0f; g_cnt[i] = 0; }
    if (i < w4) {
        float4 v = ((const float4*)W)[i];
        v.x = f2tf32f(v.x); v.y = f2tf32f(v.y);
        v.z = f2tf32f(v.z); v.w = f2tf32f(v.w);
        ((float4*)wb)[i] = v;
    }
}

// ---------------- degree + histogram, 4 edges/thread (MLP=4) ----------------
__global__ void k_deg_acc(const int* __restrict__ ei,
                          const float* __restrict__ ew, int E) {
    int q = blockIdx.x * blockDim.x + threadIdx.x;   // quad index
    if (q * 4 >= E) return;
    int4   c4 = ((const int4*)(ei + E))[q];
    float4 w4 = ((const float4*)ew)[q];
    atomicAdd(&g_deg[c4.x], w4.x);
    atomicAdd(&g_deg[c4.y], w4.y);
    atomicAdd(&g_deg[c4.z], w4.z);
    atomicAdd(&g_deg[c4.w], w4.w);
    atomicAdd(&g_cnt[c4.x], 1);
    atomicAdd(&g_cnt[c4.y], 1);
    atomicAdd(&g_cnt[c4.z], 1);
    atomicAdd(&g_cnt[c4.w], 1);
}

// ---------------- scan (rowptr + cursor) fused with dinv ----------------
__global__ void k_scan(int n, int E) {
    __shared__ int s[1024];
    int t = threadIdx.x;
    int per = (n + 1023) >> 10;
    int beg = t * per;
    int end = min(beg + per, n);
    int lsum = 0;
    for (int i = beg; i < end; i++) {
        lsum += g_cnt[i];
        float d = g_deg[i];
        g_dinv[i] = (d > 0.0f) ? rsqrtf(d) : 0.0f;
    }
    s[t] = lsum;
    __syncthreads();
    #pragma unroll
    for (int off = 1; off < 1024; off <<= 1) {
        int v = (t >= off) ? s[t - off] : 0;
        __syncthreads();
        s[t] += v;
        __syncthreads();
    }
    int pre = (t == 0) ? 0 : s[t - 1];
    for (int i = beg; i < end; i++) {
        g_rowptr[i] = pre;
        g_cursor[i] = pre;
        pre += g_cnt[i];
    }
    if (t == 1023) g_rowptr[n] = E;
}

// ---------------- CSR fill, 4 edges/thread (MLP=4) ----------------
__global__ void k_fill(const int* __restrict__ ei, const float* __restrict__ ew,
                       int E) {
    int q = blockIdx.x * blockDim.x + threadIdx.x;
    if (q * 4 >= E) return;
    int4   r4 = ((const int4*)ei)[q];
    int4   c4 = ((const int4*)(ei + E))[q];
    float4 w4 = ((const float4*)ew)[q];

    float dr0 = g_dinv[r4.x], dc0 = g_dinv[c4.x];
    float dr1 = g_dinv[r4.y], dc1 = g_dinv[c4.y];
    float dr2 = g_dinv[r4.z], dc2 = g_dinv[c4.z];
    float dr3 = g_dinv[r4.w], dc3 = g_dinv[c4.w];

    int p0 = atomicAdd(&g_cursor[c4.x], 1);
    int p1 = atomicAdd(&g_cursor[c4.y], 1);
    int p2 = atomicAdd(&g_cursor[c4.z], 1);
    int p3 = atomicAdd(&g_cursor[c4.w], 1);

    g_src[p0] = r4.x;  g_wn[p0] = dr0 * w4.x * dc0;
    g_src[p1] = r4.y;  g_wn[p1] = dr1 * w4.y * dc1;
    g_src[p2] = r4.z;  g_wn[p2] = dr2 * w4.z * dc2;
    g_src[p3] = r4.w;  g_wn[p3] = dr3 * w4.w * dc3;
}

// ---------------- tf32 tensor-core GEMM, 64x64 warp tiles, 3-stage ----------------
// A = raw fp32 x (HW truncates to tf32); B = rna-converted W.
#define BM 128
#define BN 128
#define BK 16
#define KT (D / BK)
#define AS 20
#define BS 136
#define NSTAGE 3
#define A_STAGE (BM * AS)
#define B_STAGE (BK * BS)
#define SMEM_FLOATS (NSTAGE * (A_STAGE + B_STAGE))

__device__ __forceinline__ void mma_tf32(float c[4], const uint32_t a[4],
                                         uint32_t b0, uint32_t b1) {
    asm volatile(
        "mma.sync.aligned.m16n8k8.row.col.f32.tf32.tf32.f32 "
        "{%0,%1,%2,%3}, {%4,%5,%6,%7}, {%8,%9}, {%0,%1,%2,%3};"
        : "+f"(c[0]), "+f"(c[1]), "+f"(c[2]), "+f"(c[3])
        : "r"(a[0]), "r"(a[1]), "r"(a[2]), "r"(a[3]), "r"(b0), "r"(b1));
}
__device__ __forceinline__ void cp16(uint32_t dst, const float* src, int bytes) {
    asm volatile("cp.async.cg.shared.global [%0], [%1], 16, %2;"
                 :: "r"(dst), "l"(src), "r"(bytes));
}

__global__ __launch_bounds__(128, 2)
void k_gemm_tc(const float* __restrict__ A, const float* __restrict__ B,
               float* __restrict__ H, int M) {
    extern __shared__ float smem[];
    float* AsBase = smem;                       // [NSTAGE][BM][AS]
    float* BsBase = smem + NSTAGE * A_STAGE;    // [NSTAGE][BK][BS]

    const int tid  = threadIdx.x;
    const int warp = tid >> 5, lane = tid & 31;
    const int g = lane >> 2, t = lane & 3;
    const int wy = warp >> 1;
    const int wx = warp & 1;
    const int m_warp = wy * 64;
    const int n_warp = wx * 64;
    const int m0 = blockIdx.y * BM;
    const int n0 = blockIdx.x * BN;

    uint32_t sA = (uint32_t)__cvta_generic_to_shared(AsBase);
    uint32_t sB = (uint32_t)__cvta_generic_to_shared(BsBase);

    float acc[4][8][4];
    #pragma unroll
    for (int mf = 0; mf < 4; mf++)
        #pragma unroll
        for (int nf = 0; nf < 8; nf++)
            #pragma unroll
            for (int i = 0; i < 4; i++) acc[mf][nf][i] = 0.0f;

    auto load_tiles = [&](int k0, int buf) {
        #pragma unroll
        for (int i = 0; i < 4; i++) {
            int c   = tid + i * 128;
            int row = c >> 2;
            int kq  = (c & 3) * 4;
            int gr  = m0 + row;
            const float* src = A + (size_t)gr * D + k0 + kq;
            uint32_t dst = sA + (uint32_t)((buf * A_STAGE + row * AS + kq) * 4);
            cp16(dst, src, (gr < M) ? 16 : 0);
        }
        #pragma unroll
        for (int i = 0; i < 4; i++) {
            int c   = tid + i * 128;
            int row = c >> 5;
            int nq  = (c & 31) * 4;
            const float* src = B + (size_t)(k0 + row) * D + n0 + nq;
            uint32_t dst = sB + (uint32_t)((buf * B_STAGE + row * BS + nq) * 4);
            cp16(dst, src, 16);
        }
    };

    // prologue: stages 0,1 in flight
    load_tiles(0, 0);
    asm volatile("cp.async.commit_group;");
    load_tiles(BK, 1);
    asm volatile("cp.async.commit_group;");

    for (int kt = 0; kt < KT; kt++) {
        asm volatile("cp.async.wait_group 1;");
        __syncthreads();

        // Issue NEXT load BEFORE compute so 2 tiles stay in flight under the
        // math. Stage (kt+2)%3 was computed at iter kt-1; the sync above
        // guarantees every warp is done with it.
        if (kt + 2 < KT) load_tiles((kt + 2) * BK, (kt + 2) % NSTAGE);
        asm volatile("cp.async.commit_group;");

        int buf = kt % NSTAGE;
        const float* Asb = AsBase + buf * A_STAGE;
        const float* Bsb = BsBase + buf * B_STAGE;

        #pragma unroll
        for (int ks = 0; ks < 2; ks++) {
            const int kk = ks * 8;
            uint32_t a[4][4];
            #pragma unroll
            for (int mf = 0; mf < 4; mf++) {
                int r = m_warp + mf * 16 + g;
                a[mf][0] = __float_as_uint(Asb[r * AS + kk + t]);
                a[mf][1] = __float_as_uint(Asb[(r + 8) * AS + kk + t]);
                a[mf][2] = __float_as_uint(Asb[r * AS + kk + t + 4]);
                a[mf][3] = __float_as_uint(Asb[(r + 8) * AS + kk + t + 4]);
            }
            #pragma unroll
            for (int nf = 0; nf < 8; nf++) {
                int ncol = n_warp + nf * 8 + g;
                uint32_t b0 = __float_as_uint(Bsb[(kk + t) * BS + ncol]);
                uint32_t b1 = __float_as_uint(Bsb[(kk + t + 4) * BS + ncol]);
                #pragma unroll
                for (int mf = 0; mf < 4; mf++)
                    mma_tf32(acc[mf][nf], a[mf], b0, b1);
            }
        }
    }

    #pragma unroll
    for (int mf = 0; mf < 4; mf++) {
        #pragma unroll
        for (int half = 0; half < 2; half++) {
            int r = m0 + m_warp + mf * 16 + g + half * 8;
            if (r >= M) continue;
            #pragma unroll
            for (int nf = 0; nf < 8; nf++) {
                int col = n0 + n_warp + nf * 8 + t * 2;
                *(float2*)(H + (size_t)r * D + col) =
                    make_float2(acc[mf][nf][half * 2 + 0],
                                acc[mf][nf][half * 2 + 1]);
            }
        }
    }
}

// ---------------- gather: one warp per target node ----------------
__global__ __launch_bounds__(256)
void k_gather(const float* __restrict__ bias, float* __restrict__ out, int n) {
    int w = (int)((blockIdx.x * blockDim.x + threadIdx.x) >> 5);
    int lane = threadIdx.x & 31;
    if (w >= n) return;

    int rs = g_rowptr[w];
    int re = g_rowptr[w + 1];
    float s = g_dinv[w];
    s = s * s;

    const float4* hp = (const float4*)g_h;
    const float4* bp = (const float4*)bias;

    float4 acc[4];
    #pragma unroll
    for (int i = 0; i < 4; i++) {
        int idx = lane + i * 32;
        float4 bv = bp[idx];
        float4 hv = hp[(size_t)w * D4 + idx];
        acc[i].x = bv.x + hv.x * s;
        acc[i].y = bv.y + hv.y * s;
        acc[i].z = bv.z + hv.z * s;
        acc[i].w = bv.w + hv.w * s;
    }

    for (int e = rs; e < re; e++) {
        int r = g_src[e];
        float nrm = g_wn[e];
        const float4* rp = hp + (size_t)r * D4;
        #pragma unroll
        for (int i = 0; i < 4; i++) {
            float4 v = rp[lane + i * 32];
            acc[i].x = fmaf(v.x, nrm, acc[i].x);
            acc[i].y = fmaf(v.y, nrm, acc[i].y);
            acc[i].z = fmaf(v.z, nrm, acc[i].z);
            acc[i].w = fmaf(v.w, nrm, acc[i].w);
        }
    }

    float4* op = (float4*)out + (size_t)w * D4;
    #pragma unroll
    for (int i = 0; i < 4; i++) op[lane + i * 32] = acc[i];
}

// ---------------- launch ----------------
extern "C" void kernel_launch(void* const* d_in, const int* in_sizes, int n_in,
                              void* d_out, int out_size) {
    const float* x  = (const float*)d_in[0];       // [N, 512]
    const int*   ei = (const int*)d_in[1];         // [2, E] int32
    const float* ew = (const float*)d_in[2];       // [E]
    const float* W  = (const float*)d_in[3];       // [512, 512]
    const float* b  = (const float*)d_in[4];       // [512]
    float* out = (float*)d_out;

    const int N = in_sizes[0] / D;   // 10000
    const int E = in_sizes[2];       // 160000

    float *h, *wb;
    cudaGetSymbolAddress((void**)&h,  g_h);
    cudaGetSymbolAddress((void**)&wb, g_wb);

    const int smem_bytes = SMEM_FLOATS * (int)sizeof(float);   // 56832
    cudaFuncSetAttribute(k_gemm_tc,
                         cudaFuncAttributeMaxDynamicSharedMemorySize, smem_bytes);

    // 1) fused: deg/cnt init + W tf32 conversion
    int w4 = D * D / 4;
    int init_n = (w4 > N) ? w4 : N;
    k_init<<<(init_n + 255) / 256, 256>>>(W, wb, N, w4);

    // 2) degree + histogram (4 edges/thread)
    int quads = E / 4;
    k_deg_acc<<<(quads + 255) / 256, 256>>>(ei, ew, E);

    // 3) scan (rowptr/cursor) + dinv
    k_scan<<<1, 1024>>>(N, E);

    // 4) CSR fill with precomputed norms (4 edges/thread)
    k_fill<<<(quads + 255) / 256, 256>>>(ei, ew, E);

    // 5) h = x @ W (tensor cores, 3-stage, 2 loads in flight)
    dim3 grid(D / BN, (N + BM - 1) / BM);       // (4, 79)
    k_gemm_tc<<<grid, 128, smem_bytes>>>(x, wb, h, N);

    // 6) gather: out = b + h[c]*dinv^2 + sum_e norm * h[src]
    int blocks = (N * 32 + 255) / 256;
    k_gather<<<blocks, 256>>>(b, out, N);
}